// round 14
// baseline (speedup 1.0000x reference)
#include <cuda_runtime.h>
#include <cuda_bf16.h>
#include <math.h>

#define GG   512
#define AA   24
#define NN   12288          // GG*AA
#define HID  128
#define TDIM 256
#define BBD  64
#define NL   4

// ---------------- device scratch (no allocations) ----------------
__device__ float d_h[NN*HID];
__device__ float d_Hs[NN*HID];
__device__ float d_Ht[NN*HID];
__device__ float d_agg[NN*HID];
__device__ float d_S[NN*27];
__device__ float d_C[NN*27];
__device__ float d_T[GG*HID];
__device__ float d_latc[NL*GG*HID];
__device__ float d_Wc[BBD*HID];
__device__ float d_b0[HID];

__device__ __forceinline__ float silu1(float x){ return x * (1.0f/(1.0f+__expf(-x))); }
__device__ __forceinline__ void fmas(float4& a, float p, const float4 w){
  a.x = fmaf(p, w.x, a.x); a.y = fmaf(p, w.y, a.y);
  a.z = fmaf(p, w.z, a.z); a.w = fmaf(p, w.w, a.w);
}

// ---------- Wc = W_emb @ W_lat[0:128];  b0 = b_emb@W_lat[0:128] + b_lat ----------
__global__ void k_wce(const float* __restrict__ W_emb, const float* __restrict__ b_emb,
                      const float* __restrict__ W_lat, const float* __restrict__ b_lat){
  __shared__ float row[HID];
  int r = blockIdx.x, c = threadIdx.x;
  row[c] = (r < BBD) ? W_emb[r*HID + c] : b_emb[c];
  __syncthreads();
  float s = 0.f;
  #pragma unroll 8
  for (int m = 0; m < HID; m++) s = fmaf(row[m], W_lat[m*HID + c], s);
  if (r < BBD) d_Wc[r*HID + c] = s;
  else         d_b0[c] = s + b_lat[c];
}

// ---------- T[g] = t[g] @ W_lat[144:400] + b0 ----------
__global__ void k_T(const float* __restrict__ t, const float* __restrict__ W_lat){
  __shared__ float ts[TDIM];
  int g = blockIdx.x, c = threadIdx.x;
  ts[c] = t[g*TDIM + c];
  ts[c + HID] = t[g*TDIM + c + HID];
  __syncthreads();
  float s = d_b0[c];
  const float* W = W_lat + 144*HID + c;
  #pragma unroll 8
  for (int k = 0; k < TDIM; k++) s = fmaf(ts[k], W[k*HID], s);
  d_T[g*HID + c] = s;
}

// ---------- latc[l][g] = lattices[g]@We1[l][256:262] + be1[l] + f0-cos const fold ----------
__global__ void k_latc(const float* __restrict__ lattices, const float* __restrict__ We1,
                       const float* __restrict__ be1){
  int idx = blockIdx.x*blockDim.x + threadIdx.x;
  if (idx >= NL*GG*HID) return;
  int c = idx & (HID-1);
  int g = (idx >> 7) & (GG-1);
  int l = idx >> 16;
  const float* W = We1 + (l*322 + 256)*HID + c;
  const float* la = lattices + g*6;
  float s = be1[l*HID + c];
  #pragma unroll
  for (int d = 0; d < 6; d++) s = fmaf(la[d], W[d*HID], s);
  // fold cos(0)=1 rows of the pe block: We1 rows 262+30, 262+40, 262+50
  const float* Wd0 = We1 + (l*322 + 262)*HID + c;
  s += Wd0[30*HID] + Wd0[40*HID] + Wd0[50*HID];
  d_latc[idx] = s;
}

// ---------- sincos tables (27 per node: f=1..9, 3 dims) ----------
__global__ void k_sc(const float* __restrict__ frac){
  int idx = blockIdx.x*blockDim.x + threadIdx.x;
  if (idx >= NN*27) return;
  int n = idx/27, v = idx - n*27;
  int dd = v/9, f = (v - dd*9) + 1;
  float x = frac[n*3 + dd];
  float sv, cv; sincosf(6.283185307179586f * (float)f * x, &sv, &cv);
  d_S[idx] = sv;
  d_C[idx] = cv;
}

// ---------- node init: 512 thr, 16 nodes/block, Wc in smem; h + Hs/Ht layer 0 ----------
__global__ void __launch_bounds__(512) k_init(const float* __restrict__ bb,
      const float* __restrict__ so3,
      const float* __restrict__ W_lat, const float* __restrict__ We1){
  __shared__ float Wc_s[BBD*HID];     // 32KB
  __shared__ float ins[16][80];
  __shared__ float hsm[16][HID];
  int base = blockIdx.x*16;
  int tid = threadIdx.x;
  for (int it = tid; it < BBD*HID; it += 512) Wc_s[it] = d_Wc[it];
  for (int it = tid; it < 16*80; it += 512){
    int n = it/80, p = it - n*80;
    ins[n][p] = (p < BBD) ? bb[(base+n)*BBD + p] : so3[(base+n)*16 + (p-BBD)];
  }
  __syncthreads();
  int grp = tid >> 7, c = tid & 127;
  float acc[4];
  #pragma unroll
  for (int n = 0; n < 4; n++){
    int node = base + grp*4 + n;
    acc[n] = d_T[(node/AA)*HID + c];
  }
  #pragma unroll 4
  for (int k = 0; k < BBD; k++){
    float w = Wc_s[k*HID + c];
    #pragma unroll
    for (int n = 0; n < 4; n++) acc[n] = fmaf(ins[grp*4+n][k], w, acc[n]);
  }
  #pragma unroll
  for (int k = 0; k < 16; k++){
    float w = W_lat[(HID+k)*HID + c];
    #pragma unroll
    for (int n = 0; n < 4; n++) acc[n] = fmaf(ins[grp*4+n][BBD+k], w, acc[n]);
  }
  #pragma unroll
  for (int n = 0; n < 4; n++){
    d_h[(base+grp*4+n)*HID + c] = acc[n];
    hsm[grp*4+n][c] = acc[n];
  }
  __syncthreads();
  int half = grp & 1;
  int nblk = grp >> 1;
  const float* W = We1 + (half*HID)*HID + c;
  float a2[8] = {0,0,0,0,0,0,0,0};
  #pragma unroll 4
  for (int k = 0; k < HID; k++){
    float w = W[k*HID];
    #pragma unroll
    for (int n = 0; n < 8; n++) a2[n] = fmaf(hsm[nblk*8+n][k], w, a2[n]);
  }
  float* outp = half ? d_Ht : d_Hs;
  #pragma unroll
  for (int n = 0; n < 8; n++) outp[(base+nblk*8+n)*HID + c] = a2[n];
}

// ---------- fused edge MLP (barrier-free, 2 blocks/graph, 512 thr, 4 islot x 4 jg) ----------
// pe packed: [27 sin | pad@27 | 27 cos @28..54 | pad@55] -> K = 56
// smem float offsets
#define E_WE2 0        // 16384
#define E_WD  16384    // 56*128 = 7168
#define E_B2  23552    // 128
#define E_Q   23680    // 3072 [24][128]
#define E_R   26752    // 3072
#define E_S   29824    // 768  [24][32]
#define E_C   30592    // 768
#define E_PE  31360    // 6144 [4][24][64]
#define E_G1  37504    // 12288 [4][24][128]
#define E_P   49792    // [12][4][128] = 6144
#define E_TOT 55936    // floats -> 223744 bytes

__global__ void __launch_bounds__(512,1) k_edge(const float* __restrict__ We1,
        const float* __restrict__ We2, const float* __restrict__ be2, int l){
  extern __shared__ float sm[];
  float* We2_s = sm + E_WE2;
  float* Wd_s  = sm + E_WD;
  float* b2_s  = sm + E_B2;
  float* q_s   = sm + E_Q;
  float* r_s   = sm + E_R;
  float* S_s   = sm + E_S;
  float* C_s   = sm + E_C;
  float* pe_s  = sm + E_PE;
  float* g1_s  = sm + E_G1;
  float* P_s   = sm + E_P;

  int tid = threadIdx.x;
  int g = blockIdx.x >> 1;
  int ihalf = blockIdx.x & 1;
  int nb = g*AA;

  {
    const float4* s2 = (const float4*)(We2 + l*HID*HID);
    float4* t2 = (float4*)We2_s;
    for (int it = tid; it < 4096; it += 512) t2[it] = s2[it];
  }
  // Wd image: reordered, f=0 rows dropped, pad rows 27/55 zeroed
  {
    const float* Wd = We1 + (l*322 + 262)*HID;
    for (int it = tid; it < 56*HID; it += 512){
      int r = it >> 7, c = it & 127;
      float v = 0.f;
      if (r < 27){
        int src = (r/9)*10 + (r - (r/9)*9) + 1;            // sin, f=1..9
        v = Wd[src*HID + c];
      } else if (r >= 28 && r < 55){
        int u = r - 28;
        int src = 30 + (u/9)*10 + (u - (u/9)*9) + 1;       // cos, f=1..9
        v = Wd[src*HID + c];
      }
      Wd_s[it] = v;
    }
  }
  if (tid < HID) b2_s[tid] = be2[l*HID + tid];
  const float* latp = d_latc + (l*GG + g)*HID;
  for (int it = tid; it < AA*HID; it += 512){
    q_s[it] = d_Hs[nb*HID + it] + latp[it & 127];
    r_s[it] = d_Ht[nb*HID + it];
  }
  for (int it = tid; it < 648; it += 512){
    int j = it/27, k = it - j*27;
    S_s[j*32 + k] = d_S[(nb+j)*27 + k];
    C_s[j*32 + k] = d_C[(nb+j)*27 + k];
  }
  __syncthreads();

  int lane = tid & 31, warp = tid >> 5;
  int c0 = lane * 4;
  int islot = warp & 3;          // 0..3
  int jg = warp >> 2;            // 0..3 ; j set = {jg, jg+4, ..., jg+20}
  float* peW = pe_s + islot*1536;
  float* g1W = g1_s + islot*3072;

  // ---- barrier-free over all 3 ip iterations ----
  for (int ip = 0; ip < 3; ip++){
    int i0 = ihalf*12 + ip*4;
    int i = i0 + islot;

    // warp-local pe generation (packed 27 sin + 27 cos, pads zeroed)
    if (lane < 27){
      int v = lane;
      float si = S_s[i*32+v], ci = C_s[i*32+v];
      #pragma unroll
      for (int m = 0; m < 6; m++){
        int j = jg + 4*m;
        float sj = S_s[j*32+v], cj = C_s[j*32+v];
        peW[j*64 + v]      = sj*ci - cj*si;
        peW[j*64 + 28 + v] = cj*ci + sj*si;
      }
    } else if (lane < 29){
      int off = (lane == 27) ? 27 : 55;
      #pragma unroll
      for (int m = 0; m < 6; m++) peW[(jg + 4*m)*64 + off] = 0.f;
    }
    __syncwarp();

    // phase B: g1 = silu(q_i + r_j + pe @ Wd)   (K = 56)
    {
      float4 a[6];
      #pragma unroll
      for (int m = 0; m < 6; m++) a[m] = make_float4(0,0,0,0);
      #pragma unroll 2
      for (int k = 0; k < 56; k += 4){
        float4 p[6];
        #pragma unroll
        for (int m = 0; m < 6; m++)
          p[m] = *(const float4*)(peW + (jg + 4*m)*64 + k);
        float ps[6][4];
        #pragma unroll
        for (int m = 0; m < 6; m++){
          ps[m][0]=p[m].x; ps[m][1]=p[m].y; ps[m][2]=p[m].z; ps[m][3]=p[m].w;
        }
        #pragma unroll
        for (int kk = 0; kk < 4; kk++){
          float4 w = *(const float4*)(Wd_s + (k+kk)*HID + c0);
          #pragma unroll
          for (int m = 0; m < 6; m++) fmas(a[m], ps[m][kk], w);
        }
      }
      float4 qv = *(const float4*)(q_s + i*HID + c0);
      #pragma unroll
      for (int m = 0; m < 6; m++){
        int j = jg + 4*m;
        float4 rv = *(const float4*)(r_s + j*HID + c0);
        float4 x;
        x.x = silu1(qv.x + rv.x + a[m].x);
        x.y = silu1(qv.y + rv.y + a[m].y);
        x.z = silu1(qv.z + rv.z + a[m].z);
        x.w = silu1(qv.w + rv.w + a[m].w);
        *(float4*)(g1W + j*HID + c0) = x;
      }
    }
    __syncwarp();

    // phase C: per-warp partial of sum_j silu(g1 @ We2 + b2)
    {
      float4 a[6];
      #pragma unroll
      for (int m = 0; m < 6; m++) a[m] = make_float4(0,0,0,0);
      #pragma unroll 2
      for (int k = 0; k < HID; k += 4){
        float4 p[6];
        #pragma unroll
        for (int m = 0; m < 6; m++)
          p[m] = *(const float4*)(g1W + (jg + 4*m)*HID + k);
        float ps[6][4];
        #pragma unroll
        for (int m = 0; m < 6; m++){
          ps[m][0]=p[m].x; ps[m][1]=p[m].y; ps[m][2]=p[m].z; ps[m][3]=p[m].w;
        }
        #pragma unroll
        for (int kk = 0; kk < 4; kk++){
          float4 w = *(const float4*)(We2_s + (k+kk)*HID + c0);
          #pragma unroll
          for (int m = 0; m < 6; m++) fmas(a[m], ps[m][kk], w);
        }
      }
      float4 bv = *(const float4*)(b2_s + c0);
      float4 psum = make_float4(0,0,0,0);
      #pragma unroll
      for (int m = 0; m < 6; m++){
        psum.x += silu1(a[m].x + bv.x);
        psum.y += silu1(a[m].y + bv.y);
        psum.z += silu1(a[m].z + bv.z);
        psum.w += silu1(a[m].w + bv.w);
      }
      *(float4*)(P_s + (ip*4 + islot)*512 + jg*128 + c0) = psum;
    }
  }
  __syncthreads();

  // ---- final reduction: 12 nodes x 128 cols, 4 jg-partials each ----
  for (int it = tid; it < 12*HID; it += 512){
    int n = it >> 7, c = it & 127;
    const float* pp = P_s + n*512 + c;
    float s = pp[0] + pp[128] + pp[256] + pp[384];
    d_agg[(nb + ihalf*12 + n)*HID + c] = s * (1.0f/24.0f);
  }
}

// ---------- node MLP + fused hsht for layer l+1 ----------
__global__ void __launch_bounds__(256) k_node(const float* __restrict__ Wn1,
      const float* __restrict__ bn1, const float* __restrict__ Wn2,
      const float* __restrict__ bn2, const float* __restrict__ We1, int l){
  __shared__ float nin[8][256];
  __shared__ float t1s[8][HID];
  int base = blockIdx.x*8;
  int tid = threadIdx.x;
  for (int it = tid; it < 8*256; it += 256){
    int n = it >> 8, k = it & 255;
    nin[n][k] = (k < HID) ? d_h[(base+n)*HID + k] : d_agg[(base+n)*HID + (k-HID)];
  }
  __syncthreads();
  int half = tid >> 7, c = tid & 127;
  float acc[4];
  float b1 = bn1[l*HID + c];
  #pragma unroll
  for (int n = 0; n < 4; n++) acc[n] = b1;
  const float* W1 = Wn1 + (l*256)*HID + c;
  #pragma unroll 4
  for (int k = 0; k < 256; k++){
    float w = W1[k*HID];
    #pragma unroll
    for (int n = 0; n < 4; n++) acc[n] = fmaf(nin[half*4+n][k], w, acc[n]);
  }
  #pragma unroll
  for (int n = 0; n < 4; n++) t1s[half*4+n][c] = silu1(acc[n]);
  __syncthreads();
  float b2 = bn2[l*HID + c];
  #pragma unroll
  for (int n = 0; n < 4; n++) acc[n] = b2;
  const float* W2 = Wn2 + (l*HID)*HID + c;
  #pragma unroll 4
  for (int k = 0; k < HID; k++){
    float w = W2[k*HID];
    #pragma unroll
    for (int n = 0; n < 4; n++) acc[n] = fmaf(t1s[half*4+n][k], w, acc[n]);
  }
  #pragma unroll
  for (int n = 0; n < 4; n++){
    int node = base + half*4 + n;
    float hn = nin[half*4+n][c] + silu1(acc[n]);
    d_h[node*HID + c] = hn;
    nin[half*4+n][HID + c] = hn;       // stash for fused hsht
  }
  if (l < NL-1){
    __syncthreads();
    const float* W = We1 + ((l+1)*322 + half*HID)*HID + c;
    float a2[8] = {0,0,0,0,0,0,0,0};
    #pragma unroll 4
    for (int k = 0; k < HID; k++){
      float w = W[k*HID];
      #pragma unroll
      for (int n = 0; n < 8; n++) a2[n] = fmaf(nin[n][HID + k], w, a2[n]);
    }
    float* outp = half ? d_Ht : d_Hs;
    #pragma unroll
    for (int n = 0; n < 8; n++) outp[(base+n)*HID + c] = a2[n];
  }
}

// ---------- outputs: lattice (G*6), coord (N*3), so3 (N*4) ----------
__global__ void __launch_bounds__(128) k_out(const float* __restrict__ frac,
      const float* __restrict__ W_coord, const float* __restrict__ W_lattice,
      const float* __restrict__ W_so3, float* __restrict__ out){
  __shared__ float hsm[AA*129];
  __shared__ float gf[HID];
  int g = blockIdx.x, nb = g*AA;
  int tid = threadIdx.x;
  for (int it = tid; it < AA*HID; it += 128){
    int n = it >> 7, k = it & 127;
    hsm[n*129 + k] = d_h[(nb+n)*HID + k];
  }
  __syncthreads();
  {
    float s = 0.f;
    #pragma unroll
    for (int n = 0; n < AA; n++) s += hsm[n*129 + tid];
    gf[tid] = s * (1.0f/24.0f);
  }
  __syncthreads();
  if (tid < 6){
    float s = 0.f;
    #pragma unroll 8
    for (int k = 0; k < HID; k++) s = fmaf(gf[k], W_lattice[k*6 + tid], s);
    out[g*6 + tid] = s;
  }
  if (tid < AA){
    int n = tid;
    const float* hr = hsm + n*129;
    #pragma unroll
    for (int o = 0; o < 3; o++){
      float s = 0.f;
      #pragma unroll 8
      for (int k = 0; k < HID; k++) s = fmaf(hr[k], W_coord[k*3 + o], s);
      float v = s + frac[(nb+n)*3 + o];
      out[GG*6 + (nb+n)*3 + o] = v - floorf(v);
    }
    float so[4];
    #pragma unroll
    for (int o = 0; o < 4; o++){
      float s = 0.f;
      #pragma unroll 8
      for (int k = 0; k < HID; k++) s = fmaf(hr[k], W_so3[k*4 + o], s);
      so[o] = s;
    }
    float nrm = sqrtf(so[0]*so[0] + so[1]*so[1] + so[2]*so[2] + so[3]*so[3]);
    float inv = 1.0f / nrm;
    #pragma unroll
    for (int o = 0; o < 4; o++)
      out[GG*6 + NN*3 + (nb+n)*4 + o] = so[o] * inv;
  }
}

extern "C" void kernel_launch(void* const* d_in, const int* in_sizes, int n_in,
                              void* d_out, int out_size){
  const float* t      = (const float*)d_in[0];
  const float* bb     = (const float*)d_in[1];
  const float* frac   = (const float*)d_in[2];
  const float* so3    = (const float*)d_in[3];
  const float* latt   = (const float*)d_in[4];
  const float* W_emb  = (const float*)d_in[8];
  const float* b_emb  = (const float*)d_in[9];
  const float* W_lat  = (const float*)d_in[10];
  const float* b_lat  = (const float*)d_in[11];
  const float* We1    = (const float*)d_in[12];
  const float* be1    = (const float*)d_in[13];
  const float* We2    = (const float*)d_in[14];
  const float* be2    = (const float*)d_in[15];
  const float* Wn1    = (const float*)d_in[16];
  const float* bn1    = (const float*)d_in[17];
  const float* Wn2    = (const float*)d_in[18];
  const float* bn2    = (const float*)d_in[19];
  const float* W_coord   = (const float*)d_in[20];
  const float* W_lattice = (const float*)d_in[21];
  const float* W_so3     = (const float*)d_in[22];
  float* out = (float*)d_out;

  cudaFuncSetAttribute(k_edge, cudaFuncAttributeMaxDynamicSharedMemorySize,
                       E_TOT * (int)sizeof(float));

  k_sc  <<<(NN*27 + 255)/256, 256>>>(frac);
  k_wce <<<BBD+1, 128>>>(W_emb, b_emb, W_lat, b_lat);
  k_T   <<<GG, 128>>>(t, W_lat);
  k_latc<<<(NL*GG*HID)/256, 256>>>(latt, We1, be1);
  k_init<<<NN/16, 512>>>(bb, so3, W_lat, We1);
  for (int l = 0; l < NL; l++){
    k_edge<<<GG*2, 512, E_TOT*(int)sizeof(float)>>>(We1, We2, be2, l);
    k_node<<<NN/8, 256>>>(Wn1, bn1, Wn2, bn2, We1, l);
  }
  k_out<<<GG, 128>>>(frac, W_coord, W_lattice, W_so3, out);
}

// round 15
// speedup vs baseline: 1.0455x; 1.0455x over previous
#include <cuda_runtime.h>
#include <cuda_bf16.h>
#include <math.h>

#define GG   512
#define AA   24
#define NN   12288          // GG*AA
#define HID  128
#define TDIM 256
#define BBD  64
#define NL   4

// ---------------- device scratch (no allocations) ----------------
__device__ float d_h[NN*HID];
__device__ float d_Hs[NN*HID];
__device__ float d_Ht[NN*HID];
__device__ float d_agg[NN*HID];
__device__ float d_S[NN*30];
__device__ float d_C[NN*30];
__device__ float d_T[GG*HID];
__device__ float d_latc[NL*GG*HID];
__device__ float d_Wc[BBD*HID];
__device__ float d_b0[HID];

__device__ __forceinline__ float silu1(float x){ return x * (1.0f/(1.0f+__expf(-x))); }
__device__ __forceinline__ void fmas(float4& a, float p, const float4 w){
  a.x = fmaf(p, w.x, a.x); a.y = fmaf(p, w.y, a.y);
  a.z = fmaf(p, w.z, a.z); a.w = fmaf(p, w.w, a.w);
}

// ---------- Wc = W_emb @ W_lat[0:128];  b0 = b_emb@W_lat[0:128] + b_lat ----------
__global__ void k_wce(const float* __restrict__ W_emb, const float* __restrict__ b_emb,
                      const float* __restrict__ W_lat, const float* __restrict__ b_lat){
  __shared__ float row[HID];
  int r = blockIdx.x, c = threadIdx.x;
  row[c] = (r < BBD) ? W_emb[r*HID + c] : b_emb[c];
  __syncthreads();
  float s = 0.f;
  #pragma unroll 8
  for (int m = 0; m < HID; m++) s = fmaf(row[m], W_lat[m*HID + c], s);
  if (r < BBD) d_Wc[r*HID + c] = s;
  else         d_b0[c] = s + b_lat[c];
}

// ---------- T[g] = t[g] @ W_lat[144:400] + b0 ----------
__global__ void k_T(const float* __restrict__ t, const float* __restrict__ W_lat){
  __shared__ float ts[TDIM];
  int g = blockIdx.x, c = threadIdx.x;
  ts[c] = t[g*TDIM + c];
  ts[c + HID] = t[g*TDIM + c + HID];
  __syncthreads();
  float s = d_b0[c];
  const float* W = W_lat + 144*HID + c;
  #pragma unroll 8
  for (int k = 0; k < TDIM; k++) s = fmaf(ts[k], W[k*HID], s);
  d_T[g*HID + c] = s;
}

// ---------- latc[l][g] = lattices[g] @ We1[l][256:262] + be1[l] ----------
__global__ void k_latc(const float* __restrict__ lattices, const float* __restrict__ We1,
                       const float* __restrict__ be1){
  int idx = blockIdx.x*blockDim.x + threadIdx.x;
  if (idx >= NL*GG*HID) return;
  int c = idx & (HID-1);
  int g = (idx >> 7) & (GG-1);
  int l = idx >> 16;
  const float* W = We1 + (l*322 + 256)*HID + c;
  const float* la = lattices + g*6;
  float s = be1[l*HID + c];
  #pragma unroll
  for (int d = 0; d < 6; d++) s = fmaf(la[d], W[d*HID], s);
  d_latc[idx] = s;
}

// ---------- node init: h, S/C tables, AND Hs/Ht for layer 0 (fused hsht) ----------
__global__ void __launch_bounds__(256) k_init(const float* __restrict__ bb,
      const float* __restrict__ so3, const float* __restrict__ frac,
      const float* __restrict__ W_lat, const float* __restrict__ We1){
  __shared__ float ins[8][80];
  __shared__ float hsm[8][HID];
  int base = blockIdx.x*8;
  int tid = threadIdx.x;
  for (int it = tid; it < 640; it += 256){
    int n = it/80, p = it - n*80;
    ins[n][p] = (p < BBD) ? bb[(base+n)*BBD + p] : so3[(base+n)*16 + (p-BBD)];
  }
  __syncthreads();
  int half = tid >> 7, c = tid & 127;
  float acc[4];
  #pragma unroll
  for (int n = 0; n < 4; n++){
    int node = base + half*4 + n;
    acc[n] = d_T[(node/AA)*HID + c];
  }
  #pragma unroll 4
  for (int k = 0; k < BBD; k++){
    float w = d_Wc[k*HID + c];
    #pragma unroll
    for (int n = 0; n < 4; n++) acc[n] = fmaf(ins[half*4+n][k], w, acc[n]);
  }
  #pragma unroll
  for (int k = 0; k < 16; k++){
    float w = W_lat[(HID+k)*HID + c];
    #pragma unroll
    for (int n = 0; n < 4; n++) acc[n] = fmaf(ins[half*4+n][BBD+k], w, acc[n]);
  }
  #pragma unroll
  for (int n = 0; n < 4; n++){
    d_h[(base+half*4+n)*HID + c] = acc[n];
    hsm[half*4+n][c] = acc[n];
  }
  if (tid < 240){
    int n = tid/30, k = tid - n*30;
    int dd = k/10, f = k - dd*10;
    float x = frac[(base+n)*3 + dd];
    float ang = 6.283185307179586f * (float)f * x;
    float sv, cv; sincosf(ang, &sv, &cv);
    d_S[(base+n)*30 + k] = sv;
    d_C[(base+n)*30 + k] = cv;
  }
  __syncthreads();
  // fused hsht for layer 0
  const float* W = We1 + (half*HID)*HID + c;
  float a2[8] = {0,0,0,0,0,0,0,0};
  #pragma unroll 4
  for (int k = 0; k < HID; k++){
    float w = W[k*HID];
    #pragma unroll
    for (int n = 0; n < 8; n++) a2[n] = fmaf(hsm[n][k], w, a2[n]);
  }
  float* outp = half ? d_Ht : d_Hs;
  #pragma unroll
  for (int n = 0; n < 8; n++) outp[(base+n)*HID + c] = a2[n];
}

// ---------- fused edge MLP (barrier-free, 2 blocks/graph, 512 thr, 4 islot x 4 jg) ----------
// smem float offsets
#define E_WE2 0        // 16384
#define E_WD  16384    // 7680
#define E_B2  24064    // 128
#define E_Q   24192    // 3072 [24][128]
#define E_R   27264    // 3072
#define E_S   30336    // 768  [24][32]
#define E_C   31104    // 768
#define E_PE  31872    // 6144 [4][24][64]
#define E_G1  38016    // 12288 [4][24][128]
#define E_P   50304    // [12][4][128] = 6144
#define E_TOT 56448    // floats -> 225792 bytes

__global__ void __launch_bounds__(512,1) k_edge(const float* __restrict__ We1,
        const float* __restrict__ We2, const float* __restrict__ be2, int l){
  extern __shared__ float sm[];
  float* We2_s = sm + E_WE2;
  float* Wd_s  = sm + E_WD;
  float* b2_s  = sm + E_B2;
  float* q_s   = sm + E_Q;
  float* r_s   = sm + E_R;
  float* S_s   = sm + E_S;
  float* C_s   = sm + E_C;
  float* pe_s  = sm + E_PE;
  float* g1_s  = sm + E_G1;
  float* P_s   = sm + E_P;

  int tid = threadIdx.x;
  int g = blockIdx.x >> 1;
  int ihalf = blockIdx.x & 1;
  int nb = g*AA;

  {
    const float4* s2 = (const float4*)(We2 + l*HID*HID);
    float4* t2 = (float4*)We2_s;
    for (int it = tid; it < 4096; it += 512) t2[it] = s2[it];
    const float4* sd = (const float4*)(We1 + (l*322 + 262)*HID);
    float4* td = (float4*)Wd_s;
    for (int it = tid; it < 1920; it += 512) td[it] = sd[it];
  }
  if (tid < HID) b2_s[tid] = be2[l*HID + tid];
  // q/r staging with float4 (prologue-only change vs R12)
  {
    const float4* hs4 = (const float4*)(d_Hs + (size_t)nb*HID);
    const float4* ht4 = (const float4*)(d_Ht + (size_t)nb*HID);
    const float4* lp4 = (const float4*)(d_latc + (size_t)(l*GG + g)*HID);
    float4* q4 = (float4*)q_s;
    float4* r4 = (float4*)r_s;
    for (int it = tid; it < AA*HID/4; it += 512){
      float4 hv = hs4[it];
      float4 lv = lp4[it & 31];
      hv.x += lv.x; hv.y += lv.y; hv.z += lv.z; hv.w += lv.w;
      q4[it] = hv;
      r4[it] = ht4[it];
    }
  }
  for (int it = tid; it < 720; it += 512){
    int j = it/30, k = it - j*30;
    S_s[j*32 + k] = d_S[(nb+j)*30 + k];
    C_s[j*32 + k] = d_C[(nb+j)*30 + k];
  }
  __syncthreads();

  int lane = tid & 31, warp = tid >> 5;
  int c0 = lane * 4;
  int islot = warp & 3;          // 0..3
  int jg = warp >> 2;            // 0..3 ; j set = {jg, jg+4, ..., jg+20}
  float* peW = pe_s + islot*1536;
  float* g1W = g1_s + islot*3072;

  // ---- barrier-free over all 3 ip iterations ----
  for (int ip = 0; ip < 3; ip++){
    int i0 = ihalf*12 + ip*4;
    int i = i0 + islot;

    // warp-local pe generation (only rows this warp consumes: j in its jg set)
    if (lane < 30){
      int k = lane;
      float si = S_s[i*32+k], ci = C_s[i*32+k];
      #pragma unroll
      for (int m = 0; m < 6; m++){
        int j = jg + 4*m;
        float sj = S_s[j*32+k], cj = C_s[j*32+k];
        peW[j*64 + k]      = sj*ci - cj*si;
        peW[j*64 + 30 + k] = cj*ci + sj*si;
      }
    }
    __syncwarp();

    // phase B: g1 = silu(q_i + r_j + pe @ Wd)
    {
      float4 a[6];
      #pragma unroll
      for (int m = 0; m < 6; m++) a[m] = make_float4(0,0,0,0);
      #pragma unroll 3
      for (int k = 0; k < 60; k += 4){
        float4 p[6];
        #pragma unroll
        for (int m = 0; m < 6; m++)
          p[m] = *(const float4*)(peW + (jg + 4*m)*64 + k);
        float ps[6][4];
        #pragma unroll
        for (int m = 0; m < 6; m++){
          ps[m][0]=p[m].x; ps[m][1]=p[m].y; ps[m][2]=p[m].z; ps[m][3]=p[m].w;
        }
        #pragma unroll
        for (int kk = 0; kk < 4; kk++){
          float4 w = *(const float4*)(Wd_s + (k+kk)*HID + c0);
          #pragma unroll
          for (int m = 0; m < 6; m++) fmas(a[m], ps[m][kk], w);
        }
      }
      float4 qv = *(const float4*)(q_s + i*HID + c0);
      #pragma unroll
      for (int m = 0; m < 6; m++){
        int j = jg + 4*m;
        float4 rv = *(const float4*)(r_s + j*HID + c0);
        float4 x;
        x.x = silu1(qv.x + rv.x + a[m].x);
        x.y = silu1(qv.y + rv.y + a[m].y);
        x.z = silu1(qv.z + rv.z + a[m].z);
        x.w = silu1(qv.w + rv.w + a[m].w);
        *(float4*)(g1W + j*HID + c0) = x;
      }
    }
    __syncwarp();

    // phase C: per-warp partial of sum_j silu(g1 @ We2 + b2)
    {
      float4 a[6];
      #pragma unroll
      for (int m = 0; m < 6; m++) a[m] = make_float4(0,0,0,0);
      #pragma unroll 2
      for (int k = 0; k < HID; k += 4){
        float4 p[6];
        #pragma unroll
        for (int m = 0; m < 6; m++)
          p[m] = *(const float4*)(g1W + (jg + 4*m)*HID + k);
        float ps[6][4];
        #pragma unroll
        for (int m = 0; m < 6; m++){
          ps[m][0]=p[m].x; ps[m][1]=p[m].y; ps[m][2]=p[m].z; ps[m][3]=p[m].w;
        }
        #pragma unroll
        for (int kk = 0; kk < 4; kk++){
          float4 w = *(const float4*)(We2_s + (k+kk)*HID + c0);
          #pragma unroll
          for (int m = 0; m < 6; m++) fmas(a[m], ps[m][kk], w);
        }
      }
      float4 bv = *(const float4*)(b2_s + c0);
      float4 psum = make_float4(0,0,0,0);
      #pragma unroll
      for (int m = 0; m < 6; m++){
        psum.x += silu1(a[m].x + bv.x);
        psum.y += silu1(a[m].y + bv.y);
        psum.z += silu1(a[m].z + bv.z);
        psum.w += silu1(a[m].w + bv.w);
      }
      // private slot: [node-in-block = ip*4+islot][jg][c]
      *(float4*)(P_s + (ip*4 + islot)*512 + jg*128 + c0) = psum;
    }
  }
  __syncthreads();

  // ---- final reduction: 12 nodes x 128 cols, 4 jg-partials each ----
  for (int it = tid; it < 12*HID; it += 512){
    int n = it >> 7, c = it & 127;
    const float* pp = P_s + n*512 + c;
    float s = pp[0] + pp[128] + pp[256] + pp[384];
    d_agg[(nb + ihalf*12 + n)*HID + c] = s * (1.0f/24.0f);
  }
}

// ---------- node MLP + fused hsht for layer l+1 ----------
__global__ void __launch_bounds__(256) k_node(const float* __restrict__ Wn1,
      const float* __restrict__ bn1, const float* __restrict__ Wn2,
      const float* __restrict__ bn2, const float* __restrict__ We1, int l){
  __shared__ float nin[8][256];
  __shared__ float t1s[8][HID];
  int base = blockIdx.x*8;
  int tid = threadIdx.x;
  for (int it = tid; it < 8*256; it += 256){
    int n = it >> 8, k = it & 255;
    nin[n][k] = (k < HID) ? d_h[(base+n)*HID + k] : d_agg[(base+n)*HID + (k-HID)];
  }
  __syncthreads();
  int half = tid >> 7, c = tid & 127;
  float acc[4];
  float b1 = bn1[l*HID + c];
  #pragma unroll
  for (int n = 0; n < 4; n++) acc[n] = b1;
  const float* W1 = Wn1 + (l*256)*HID + c;
  #pragma unroll 4
  for (int k = 0; k < 256; k++){
    float w = W1[k*HID];
    #pragma unroll
    for (int n = 0; n < 4; n++) acc[n] = fmaf(nin[half*4+n][k], w, acc[n]);
  }
  #pragma unroll
  for (int n = 0; n < 4; n++) t1s[half*4+n][c] = silu1(acc[n]);
  __syncthreads();
  float b2 = bn2[l*HID + c];
  #pragma unroll
  for (int n = 0; n < 4; n++) acc[n] = b2;
  const float* W2 = Wn2 + (l*HID)*HID + c;
  #pragma unroll 4
  for (int k = 0; k < HID; k++){
    float w = W2[k*HID];
    #pragma unroll
    for (int n = 0; n < 4; n++) acc[n] = fmaf(t1s[half*4+n][k], w, acc[n]);
  }
  #pragma unroll
  for (int n = 0; n < 4; n++){
    int node = base + half*4 + n;
    float hn = nin[half*4+n][c] + silu1(acc[n]);
    d_h[node*HID + c] = hn;
    nin[half*4+n][HID + c] = hn;       // stash for fused hsht
  }
  if (l < NL-1){
    __syncthreads();
    const float* W = We1 + ((l+1)*322 + half*HID)*HID + c;
    float a2[8] = {0,0,0,0,0,0,0,0};
    #pragma unroll 4
    for (int k = 0; k < HID; k++){
      float w = W[k*HID];
      #pragma unroll
      for (int n = 0; n < 8; n++) a2[n] = fmaf(nin[n][HID + k], w, a2[n]);
    }
    float* outp = half ? d_Ht : d_Hs;
    #pragma unroll
    for (int n = 0; n < 8; n++) outp[(base+n)*HID + c] = a2[n];
  }
}

// ---------- outputs: lattice (G*6), coord (N*3), so3 (N*4) ----------
__global__ void __launch_bounds__(128) k_out(const float* __restrict__ frac,
      const float* __restrict__ W_coord, const float* __restrict__ W_lattice,
      const float* __restrict__ W_so3, float* __restrict__ out){
  __shared__ float hsm[AA*129];
  __shared__ float gf[HID];
  int g = blockIdx.x, nb = g*AA;
  int tid = threadIdx.x;
  for (int it = tid; it < AA*HID; it += 128){
    int n = it >> 7, k = it & 127;
    hsm[n*129 + k] = d_h[(nb+n)*HID + k];
  }
  __syncthreads();
  {
    float s = 0.f;
    #pragma unroll
    for (int n = 0; n < AA; n++) s += hsm[n*129 + tid];
    gf[tid] = s * (1.0f/24.0f);
  }
  __syncthreads();
  if (tid < 6){
    float s = 0.f;
    #pragma unroll 8
    for (int k = 0; k < HID; k++) s = fmaf(gf[k], W_lattice[k*6 + tid], s);
    out[g*6 + tid] = s;
  }
  if (tid < AA){
    int n = tid;
    const float* hr = hsm + n*129;
    #pragma unroll
    for (int o = 0; o < 3; o++){
      float s = 0.f;
      #pragma unroll 8
      for (int k = 0; k < HID; k++) s = fmaf(hr[k], W_coord[k*3 + o], s);
      float v = s + frac[(nb+n)*3 + o];
      out[GG*6 + (nb+n)*3 + o] = v - floorf(v);
    }
    float so[4];
    #pragma unroll
    for (int o = 0; o < 4; o++){
      float s = 0.f;
      #pragma unroll 8
      for (int k = 0; k < HID; k++) s = fmaf(hr[k], W_so3[k*4 + o], s);
      so[o] = s;
    }
    float nrm = sqrtf(so[0]*so[0] + so[1]*so[1] + so[2]*so[2] + so[3]*so[3]);
    float inv = 1.0f / nrm;
    #pragma unroll
    for (int o = 0; o < 4; o++)
      out[GG*6 + NN*3 + (nb+n)*4 + o] = so[o] * inv;
  }
}

extern "C" void kernel_launch(void* const* d_in, const int* in_sizes, int n_in,
                              void* d_out, int out_size){
  const float* t      = (const float*)d_in[0];
  const float* bb     = (const float*)d_in[1];
  const float* frac   = (const float*)d_in[2];
  const float* so3    = (const float*)d_in[3];
  const float* latt   = (const float*)d_in[4];
  const float* W_emb  = (const float*)d_in[8];
  const float* b_emb  = (const float*)d_in[9];
  const float* W_lat  = (const float*)d_in[10];
  const float* b_lat  = (const float*)d_in[11];
  const float* We1    = (const float*)d_in[12];
  const float* be1    = (const float*)d_in[13];
  const float* We2    = (const float*)d_in[14];
  const float* be2    = (const float*)d_in[15];
  const float* Wn1    = (const float*)d_in[16];
  const float* bn1    = (const float*)d_in[17];
  const float* Wn2    = (const float*)d_in[18];
  const float* bn2    = (const float*)d_in[19];
  const float* W_coord   = (const float*)d_in[20];
  const float* W_lattice = (const float*)d_in[21];
  const float* W_so3     = (const float*)d_in[22];
  float* out = (float*)d_out;

  cudaFuncSetAttribute(k_edge, cudaFuncAttributeMaxDynamicSharedMemorySize,
                       E_TOT * (int)sizeof(float));

  k_wce <<<BBD+1, 128>>>(W_emb, b_emb, W_lat, b_lat);
  k_T   <<<GG, 128>>>(t, W_lat);
  k_latc<<<(NL*GG*HID)/256, 256>>>(latt, We1, be1);
  k_init<<<NN/8, 256>>>(bb, so3, frac, W_lat, We1);
  for (int l = 0; l < NL; l++){
    k_edge<<<GG*2, 512, E_TOT*(int)sizeof(float)>>>(We1, We2, be2, l);
    k_node<<<NN/8, 256>>>(Wn1, bn1, Wn2, bn2, We1, l);
  }
  k_out<<<GG, 128>>>(frac, W_coord, W_lattice, W_so3, out);
}

// round 16
// speedup vs baseline: 1.0485x; 1.0029x over previous
#include <cuda_runtime.h>
#include <cuda_bf16.h>
#include <math.h>

#define GG   512
#define AA   24
#define NN   12288          // GG*AA
#define HID  128
#define TDIM 256
#define BBD  64
#define NL   4

// ---------------- device scratch (no allocations) ----------------
__device__ float d_h[NN*HID];
__device__ float d_Hs[NN*HID];
__device__ float d_Ht[NN*HID];
__device__ float d_agg[NN*HID];
__device__ float d_S[NN*32];   // stride-32 padded (cols 30,31 unused)
__device__ float d_C[NN*32];
__device__ float d_T[GG*HID];
__device__ float d_latc[NL*GG*HID];
__device__ float d_Wc[BBD*HID];
__device__ float d_b0[HID];

__device__ __forceinline__ float silu1(float x){ return x * (1.0f/(1.0f+__expf(-x))); }
__device__ __forceinline__ void fmas(float4& a, float p, const float4 w){
  a.x = fmaf(p, w.x, a.x); a.y = fmaf(p, w.y, a.y);
  a.z = fmaf(p, w.z, a.z); a.w = fmaf(p, w.w, a.w);
}

// ---------- Wc = W_emb @ W_lat[0:128];  b0 = b_emb@W_lat[0:128] + b_lat ----------
__global__ void k_wce(const float* __restrict__ W_emb, const float* __restrict__ b_emb,
                      const float* __restrict__ W_lat, const float* __restrict__ b_lat){
  __shared__ float row[HID];
  int r = blockIdx.x, c = threadIdx.x;
  row[c] = (r < BBD) ? W_emb[r*HID + c] : b_emb[c];
  __syncthreads();
  float s = 0.f;
  #pragma unroll 8
  for (int m = 0; m < HID; m++) s = fmaf(row[m], W_lat[m*HID + c], s);
  if (r < BBD) d_Wc[r*HID + c] = s;
  else         d_b0[c] = s + b_lat[c];
}

// ---------- T[g] = t[g] @ W_lat[144:400] + b0 ----------
__global__ void k_T(const float* __restrict__ t, const float* __restrict__ W_lat){
  __shared__ float ts[TDIM];
  int g = blockIdx.x, c = threadIdx.x;
  ts[c] = t[g*TDIM + c];
  ts[c + HID] = t[g*TDIM + c + HID];
  __syncthreads();
  float s = d_b0[c];
  const float* W = W_lat + 144*HID + c;
  #pragma unroll 8
  for (int k = 0; k < TDIM; k++) s = fmaf(ts[k], W[k*HID], s);
  d_T[g*HID + c] = s;
}

// ---------- latc[l][g] = lattices[g] @ We1[l][256:262] + be1[l] ----------
__global__ void k_latc(const float* __restrict__ lattices, const float* __restrict__ We1,
                       const float* __restrict__ be1){
  int idx = blockIdx.x*blockDim.x + threadIdx.x;
  if (idx >= NL*GG*HID) return;
  int c = idx & (HID-1);
  int g = (idx >> 7) & (GG-1);
  int l = idx >> 16;
  const float* W = We1 + (l*322 + 256)*HID + c;
  const float* la = lattices + g*6;
  float s = be1[l*HID + c];
  #pragma unroll
  for (int d = 0; d < 6; d++) s = fmaf(la[d], W[d*HID], s);
  d_latc[idx] = s;
}

// ---------- node init: h, S/C tables (stride 32), AND Hs/Ht for layer 0 ----------
__global__ void __launch_bounds__(256) k_init(const float* __restrict__ bb,
      const float* __restrict__ so3, const float* __restrict__ frac,
      const float* __restrict__ W_lat, const float* __restrict__ We1){
  __shared__ float ins[8][80];
  __shared__ float hsm[8][HID];
  int base = blockIdx.x*8;
  int tid = threadIdx.x;
  for (int it = tid; it < 640; it += 256){
    int n = it/80, p = it - n*80;
    ins[n][p] = (p < BBD) ? bb[(base+n)*BBD + p] : so3[(base+n)*16 + (p-BBD)];
  }
  __syncthreads();
  int half = tid >> 7, c = tid & 127;
  float acc[4];
  #pragma unroll
  for (int n = 0; n < 4; n++){
    int node = base + half*4 + n;
    acc[n] = d_T[(node/AA)*HID + c];
  }
  #pragma unroll 4
  for (int k = 0; k < BBD; k++){
    float w = d_Wc[k*HID + c];
    #pragma unroll
    for (int n = 0; n < 4; n++) acc[n] = fmaf(ins[half*4+n][k], w, acc[n]);
  }
  #pragma unroll
  for (int k = 0; k < 16; k++){
    float w = W_lat[(HID+k)*HID + c];
    #pragma unroll
    for (int n = 0; n < 4; n++) acc[n] = fmaf(ins[half*4+n][BBD+k], w, acc[n]);
  }
  #pragma unroll
  for (int n = 0; n < 4; n++){
    d_h[(base+half*4+n)*HID + c] = acc[n];
    hsm[half*4+n][c] = acc[n];
  }
  if (tid < 240){
    int n = tid/30, k = tid - n*30;
    int dd = k/10, f = k - dd*10;
    float x = frac[(base+n)*3 + dd];
    float ang = 6.283185307179586f * (float)f * x;
    float sv, cv; sincosf(ang, &sv, &cv);
    d_S[(base+n)*32 + k] = sv;
    d_C[(base+n)*32 + k] = cv;
  }
  __syncthreads();
  // fused hsht for layer 0
  const float* W = We1 + (half*HID)*HID + c;
  float a2[8] = {0,0,0,0,0,0,0,0};
  #pragma unroll 4
  for (int k = 0; k < HID; k++){
    float w = W[k*HID];
    #pragma unroll
    for (int n = 0; n < 8; n++) a2[n] = fmaf(hsm[n][k], w, a2[n]);
  }
  float* outp = half ? d_Ht : d_Hs;
  #pragma unroll
  for (int n = 0; n < 8; n++) outp[(base+n)*HID + c] = a2[n];
}

// ---------- fused edge MLP (barrier-free, 2 blocks/graph, 512 thr, 4 islot x 4 jg) ----------
// smem float offsets
#define E_WE2 0        // 16384
#define E_WD  16384    // 7680
#define E_B2  24064    // 128
#define E_Q   24192    // 3072 [24][128]
#define E_R   27264    // 3072
#define E_S   30336    // 768  [24][32]
#define E_C   31104    // 768
#define E_PE  31872    // 6144 [4][24][64]
#define E_G1  38016    // 12288 [4][24][128]
#define E_P   50304    // [12][4][128] = 6144
#define E_TOT 56448    // floats -> 225792 bytes

__global__ void __launch_bounds__(512,1) k_edge(const float* __restrict__ We1,
        const float* __restrict__ We2, const float* __restrict__ be2, int l){
  extern __shared__ float sm[];
  float* We2_s = sm + E_WE2;
  float* Wd_s  = sm + E_WD;
  float* b2_s  = sm + E_B2;
  float* q_s   = sm + E_Q;
  float* r_s   = sm + E_R;
  float* S_s   = sm + E_S;
  float* C_s   = sm + E_C;
  float* pe_s  = sm + E_PE;
  float* g1_s  = sm + E_G1;
  float* P_s   = sm + E_P;

  int tid = threadIdx.x;
  int g = blockIdx.x >> 1;
  int ihalf = blockIdx.x & 1;
  int nb = g*AA;

  {
    const float4* s2 = (const float4*)(We2 + l*HID*HID);
    float4* t2 = (float4*)We2_s;
    for (int it = tid; it < 4096; it += 512) t2[it] = s2[it];
    const float4* sd = (const float4*)(We1 + (l*322 + 262)*HID);
    float4* td = (float4*)Wd_s;
    for (int it = tid; it < 1920; it += 512) td[it] = sd[it];
  }
  if (tid < HID) b2_s[tid] = be2[l*HID + tid];
  // q/r staging with float4
  {
    const float4* hs4 = (const float4*)(d_Hs + (size_t)nb*HID);
    const float4* ht4 = (const float4*)(d_Ht + (size_t)nb*HID);
    const float4* lp4 = (const float4*)(d_latc + (size_t)(l*GG + g)*HID);
    float4* q4 = (float4*)q_s;
    float4* r4 = (float4*)r_s;
    for (int it = tid; it < AA*HID/4; it += 512){
      float4 hv = hs4[it];
      float4 lv = lp4[it & 31];
      hv.x += lv.x; hv.y += lv.y; hv.z += lv.z; hv.w += lv.w;
      q4[it] = hv;
      r4[it] = ht4[it];
    }
  }
  // S/C staging with float4 (stride-32 padded tables)
  {
    const float4* sS = (const float4*)(d_S + (size_t)nb*32);
    const float4* sC = (const float4*)(d_C + (size_t)nb*32);
    float4* tS = (float4*)S_s;
    float4* tC = (float4*)C_s;
    for (int it = tid; it < 192; it += 512){
      tS[it] = sS[it];
      tC[it] = sC[it];
    }
  }
  __syncthreads();

  int lane = tid & 31, warp = tid >> 5;
  int c0 = lane * 4;
  int islot = warp & 3;          // 0..3
  int jg = warp >> 2;            // 0..3 ; j set = {jg, jg+4, ..., jg+20}
  float* peW = pe_s + islot*1536;
  float* g1W = g1_s + islot*3072;

  // ---- barrier-free over all 3 ip iterations ----
  for (int ip = 0; ip < 3; ip++){
    int i0 = ihalf*12 + ip*4;
    int i = i0 + islot;

    // warp-local pe generation (only rows this warp consumes: j in its jg set)
    if (lane < 30){
      int k = lane;
      float si = S_s[i*32+k], ci = C_s[i*32+k];
      #pragma unroll
      for (int m = 0; m < 6; m++){
        int j = jg + 4*m;
        float sj = S_s[j*32+k], cj = C_s[j*32+k];
        peW[j*64 + k]      = sj*ci - cj*si;
        peW[j*64 + 30 + k] = cj*ci + sj*si;
      }
    }
    __syncwarp();

    // phase B: g1 = silu(q_i + r_j + pe @ Wd)
    {
      float4 a[6];
      #pragma unroll
      for (int m = 0; m < 6; m++) a[m] = make_float4(0,0,0,0);
      #pragma unroll 3
      for (int k = 0; k < 60; k += 4){
        float4 p[6];
        #pragma unroll
        for (int m = 0; m < 6; m++)
          p[m] = *(const float4*)(peW + (jg + 4*m)*64 + k);
        float ps[6][4];
        #pragma unroll
        for (int m = 0; m < 6; m++){
          ps[m][0]=p[m].x; ps[m][1]=p[m].y; ps[m][2]=p[m].z; ps[m][3]=p[m].w;
        }
        #pragma unroll
        for (int kk = 0; kk < 4; kk++){
          float4 w = *(const float4*)(Wd_s + (k+kk)*HID + c0);
          #pragma unroll
          for (int m = 0; m < 6; m++) fmas(a[m], ps[m][kk], w);
        }
      }
      float4 qv = *(const float4*)(q_s + i*HID + c0);
      #pragma unroll
      for (int m = 0; m < 6; m++){
        int j = jg + 4*m;
        float4 rv = *(const float4*)(r_s + j*HID + c0);
        float4 x;
        x.x = silu1(qv.x + rv.x + a[m].x);
        x.y = silu1(qv.y + rv.y + a[m].y);
        x.z = silu1(qv.z + rv.z + a[m].z);
        x.w = silu1(qv.w + rv.w + a[m].w);
        *(float4*)(g1W + j*HID + c0) = x;
      }
    }
    __syncwarp();

    // phase C: per-warp partial of sum_j silu(g1 @ We2 + b2)
    {
      float4 a[6];
      #pragma unroll
      for (int m = 0; m < 6; m++) a[m] = make_float4(0,0,0,0);
      #pragma unroll 2
      for (int k = 0; k < HID; k += 4){
        float4 p[6];
        #pragma unroll
        for (int m = 0; m < 6; m++)
          p[m] = *(const float4*)(g1W + (jg + 4*m)*HID + k);
        float ps[6][4];
        #pragma unroll
        for (int m = 0; m < 6; m++){
          ps[m][0]=p[m].x; ps[m][1]=p[m].y; ps[m][2]=p[m].z; ps[m][3]=p[m].w;
        }
        #pragma unroll
        for (int kk = 0; kk < 4; kk++){
          float4 w = *(const float4*)(We2_s + (k+kk)*HID + c0);
          #pragma unroll
          for (int m = 0; m < 6; m++) fmas(a[m], ps[m][kk], w);
        }
      }
      float4 bv = *(const float4*)(b2_s + c0);
      float4 psum = make_float4(0,0,0,0);
      #pragma unroll
      for (int m = 0; m < 6; m++){
        psum.x += silu1(a[m].x + bv.x);
        psum.y += silu1(a[m].y + bv.y);
        psum.z += silu1(a[m].z + bv.z);
        psum.w += silu1(a[m].w + bv.w);
      }
      // private slot: [node-in-block = ip*4+islot][jg][c]
      *(float4*)(P_s + (ip*4 + islot)*512 + jg*128 + c0) = psum;
    }
  }
  __syncthreads();

  // ---- final reduction: 12 nodes x 128 cols, 4 jg-partials each (float4) ----
  {
    float4* agg4 = (float4*)(d_agg + (size_t)(nb + ihalf*12)*HID);
    for (int it = tid; it < 12*HID/4; it += 512){
      int n = it >> 5, cq = it & 31;               // cq = c/4
      const float4* pp = (const float4*)(P_s + n*512) + cq;
      float4 s0 = pp[0], s1 = pp[32], s2 = pp[64], s3 = pp[96];
      float4 o;
      o.x = (s0.x + s1.x + s2.x + s3.x) * (1.0f/24.0f);
      o.y = (s0.y + s1.y + s2.y + s3.y) * (1.0f/24.0f);
      o.z = (s0.z + s1.z + s2.z + s3.z) * (1.0f/24.0f);
      o.w = (s0.w + s1.w + s2.w + s3.w) * (1.0f/24.0f);
      agg4[it] = o;
    }
  }
}

// ---------- node MLP + fused hsht for layer l+1 ----------
__global__ void __launch_bounds__(256) k_node(const float* __restrict__ Wn1,
      const float* __restrict__ bn1, const float* __restrict__ Wn2,
      const float* __restrict__ bn2, const float* __restrict__ We1, int l){
  __shared__ float nin[8][256];
  __shared__ float t1s[8][HID];
  int base = blockIdx.x*8;
  int tid = threadIdx.x;
  for (int it = tid; it < 8*256; it += 256){
    int n = it >> 8, k = it & 255;
    nin[n][k] = (k < HID) ? d_h[(base+n)*HID + k] : d_agg[(base+n)*HID + (k-HID)];
  }
  __syncthreads();
  int half = tid >> 7, c = tid & 127;
  float acc[4];
  float b1 = bn1[l*HID + c];
  #pragma unroll
  for (int n = 0; n < 4; n++) acc[n] = b1;
  const float* W1 = Wn1 + (l*256)*HID + c;
  #pragma unroll 4
  for (int k = 0; k < 256; k++){
    float w = W1[k*HID];
    #pragma unroll
    for (int n = 0; n < 4; n++) acc[n] = fmaf(nin[half*4+n][k], w, acc[n]);
  }
  #pragma unroll
  for (int n = 0; n < 4; n++) t1s[half*4+n][c] = silu1(acc[n]);
  __syncthreads();
  float b2 = bn2[l*HID + c];
  #pragma unroll
  for (int n = 0; n < 4; n++) acc[n] = b2;
  const float* W2 = Wn2 + (l*HID)*HID + c;
  #pragma unroll 4
  for (int k = 0; k < HID; k++){
    float w = W2[k*HID];
    #pragma unroll
    for (int n = 0; n < 4; n++) acc[n] = fmaf(t1s[half*4+n][k], w, acc[n]);
  }
  #pragma unroll
  for (int n = 0; n < 4; n++){
    int node = base + half*4 + n;
    float hn = nin[half*4+n][c] + silu1(acc[n]);
    d_h[node*HID + c] = hn;
    nin[half*4+n][HID + c] = hn;       // stash for fused hsht
  }
  if (l < NL-1){
    __syncthreads();
    const float* W = We1 + ((l+1)*322 + half*HID)*HID + c;
    float a2[8] = {0,0,0,0,0,0,0,0};
    #pragma unroll 4
    for (int k = 0; k < HID; k++){
      float w = W[k*HID];
      #pragma unroll
      for (int n = 0; n < 8; n++) a2[n] = fmaf(nin[n][HID + k], w, a2[n]);
    }
    float* outp = half ? d_Ht : d_Hs;
    #pragma unroll
    for (int n = 0; n < 8; n++) outp[(base+n)*HID + c] = a2[n];
  }
}

// ---------- outputs: lattice (G*6), coord (N*3), so3 (N*4) ----------
__global__ void __launch_bounds__(128) k_out(const float* __restrict__ frac,
      const float* __restrict__ W_coord, const float* __restrict__ W_lattice,
      const float* __restrict__ W_so3, float* __restrict__ out){
  __shared__ float hsm[AA*129];
  __shared__ float gf[HID];
  int g = blockIdx.x, nb = g*AA;
  int tid = threadIdx.x;
  for (int it = tid; it < AA*HID; it += 128){
    int n = it >> 7, k = it & 127;
    hsm[n*129 + k] = d_h[(nb+n)*HID + k];
  }
  __syncthreads();
  {
    float s = 0.f;
    #pragma unroll
    for (int n = 0; n < AA; n++) s += hsm[n*129 + tid];
    gf[tid] = s * (1.0f/24.0f);
  }
  __syncthreads();
  if (tid < 6){
    float s = 0.f;
    #pragma unroll 8
    for (int k = 0; k < HID; k++) s = fmaf(gf[k], W_lattice[k*6 + tid], s);
    out[g*6 + tid] = s;
  }
  if (tid < AA){
    int n = tid;
    const float* hr = hsm + n*129;
    #pragma unroll
    for (int o = 0; o < 3; o++){
      float s = 0.f;
      #pragma unroll 8
      for (int k = 0; k < HID; k++) s = fmaf(hr[k], W_coord[k*3 + o], s);
      float v = s + frac[(nb+n)*3 + o];
      out[GG*6 + (nb+n)*3 + o] = v - floorf(v);
    }
    float so[4];
    #pragma unroll
    for (int o = 0; o < 4; o++){
      float s = 0.f;
      #pragma unroll 8
      for (int k = 0; k < HID; k++) s = fmaf(hr[k], W_so3[k*4 + o], s);
      so[o] = s;
    }
    float nrm = sqrtf(so[0]*so[0] + so[1]*so[1] + so[2]*so[2] + so[3]*so[3]);
    float inv = 1.0f / nrm;
    #pragma unroll
    for (int o = 0; o < 4; o++)
      out[GG*6 + NN*3 + (nb+n)*4 + o] = so[o] * inv;
  }
}

extern "C" void kernel_launch(void* const* d_in, const int* in_sizes, int n_in,
                              void* d_out, int out_size){
  const float* t      = (const float*)d_in[0];
  const float* bb     = (const float*)d_in[1];
  const float* frac   = (const float*)d_in[2];
  const float* so3    = (const float*)d_in[3];
  const float* latt   = (const float*)d_in[4];
  const float* W_emb  = (const float*)d_in[8];
  const float* b_emb  = (const float*)d_in[9];
  const float* W_lat  = (const float*)d_in[10];
  const float* b_lat  = (const float*)d_in[11];
  const float* We1    = (const float*)d_in[12];
  const float* be1    = (const float*)d_in[13];
  const float* We2    = (const float*)d_in[14];
  const float* be2    = (const float*)d_in[15];
  const float* Wn1    = (const float*)d_in[16];
  const float* bn1    = (const float*)d_in[17];
  const float* Wn2    = (const float*)d_in[18];
  const float* bn2    = (const float*)d_in[19];
  const float* W_coord   = (const float*)d_in[20];
  const float* W_lattice = (const float*)d_in[21];
  const float* W_so3     = (const float*)d_in[22];
  float* out = (float*)d_out;

  cudaFuncSetAttribute(k_edge, cudaFuncAttributeMaxDynamicSharedMemorySize,
                       E_TOT * (int)sizeof(float));

  k_wce <<<BBD+1, 128>>>(W_emb, b_emb, W_lat, b_lat);
  k_T   <<<GG, 128>>>(t, W_lat);
  k_latc<<<(NL*GG*HID)/256, 256>>>(latt, We1, be1);
  k_init<<<NN/8, 256>>>(bb, so3, frac, W_lat, We1);
  for (int l = 0; l < NL; l++){
    k_edge<<<GG*2, 512, E_TOT*(int)sizeof(float)>>>(We1, We2, be2, l);
    k_node<<<NN/8, 256>>>(Wn1, bn1, Wn2, bn2, We1, l);
  }
  k_out<<<GG, 128>>>(frac, W_coord, W_lattice, W_so3, out);
}

// round 17
// speedup vs baseline: 1.0598x; 1.0107x over previous
#include <cuda_runtime.h>
#include <cuda_bf16.h>
#include <math.h>

#define GG   512
#define AA   24
#define NN   12288          // GG*AA
#define HID  128
#define TDIM 256
#define BBD  64
#define NL   4

// ---------------- device scratch (no allocations) ----------------
__device__ float d_h[NN*HID];
__device__ float d_Hs[NN*HID];
__device__ float d_Ht[NN*HID];
__device__ float d_agg[NN*HID];
__device__ float d_S[NN*32];   // stride-32 padded (cols 30,31 unused)
__device__ float d_C[NN*32];
__device__ float d_T[GG*HID];
__device__ float d_latc[NL*GG*HID];
__device__ float d_Wc[BBD*HID];
__device__ float d_b0[HID];

__device__ __forceinline__ float silu1(float x){ return x * (1.0f/(1.0f+__expf(-x))); }
__device__ __forceinline__ void fmas(float4& a, float p, const float4 w){
  a.x = fmaf(p, w.x, a.x); a.y = fmaf(p, w.y, a.y);
  a.z = fmaf(p, w.z, a.z); a.w = fmaf(p, w.w, a.w);
}

// ---------- Wc = W_emb @ W_lat[0:128];  b0 = b_emb@W_lat[0:128] + b_lat ----------
__global__ void k_wce(const float* __restrict__ W_emb, const float* __restrict__ b_emb,
                      const float* __restrict__ W_lat, const float* __restrict__ b_lat){
  __shared__ float row[HID];
  int r = blockIdx.x, c = threadIdx.x;
  row[c] = (r < BBD) ? W_emb[r*HID + c] : b_emb[c];
  __syncthreads();
  float s = 0.f;
  #pragma unroll 8
  for (int m = 0; m < HID; m++) s = fmaf(row[m], W_lat[m*HID + c], s);
  if (r < BBD) d_Wc[r*HID + c] = s;
  else         d_b0[c] = s + b_lat[c];
}

// ---------- T[g] = t[g] @ W_lat[144:400] + b0 ----------
__global__ void k_T(const float* __restrict__ t, const float* __restrict__ W_lat){
  __shared__ float ts[TDIM];
  int g = blockIdx.x, c = threadIdx.x;
  ts[c] = t[g*TDIM + c];
  ts[c + HID] = t[g*TDIM + c + HID];
  __syncthreads();
  float s = d_b0[c];
  const float* W = W_lat + 144*HID + c;
  #pragma unroll 8
  for (int k = 0; k < TDIM; k++) s = fmaf(ts[k], W[k*HID], s);
  d_T[g*HID + c] = s;
}

// ---------- latc[l][g] = lattices[g] @ We1[l][256:262] + be1[l] ----------
__global__ void k_latc(const float* __restrict__ lattices, const float* __restrict__ We1,
                       const float* __restrict__ be1){
  int idx = blockIdx.x*blockDim.x + threadIdx.x;
  if (idx >= NL*GG*HID) return;
  int c = idx & (HID-1);
  int g = (idx >> 7) & (GG-1);
  int l = idx >> 16;
  const float* W = We1 + (l*322 + 256)*HID + c;
  const float* la = lattices + g*6;
  float s = be1[l*HID + c];
  #pragma unroll
  for (int d = 0; d < 6; d++) s = fmaf(la[d], W[d*HID], s);
  d_latc[idx] = s;
}

// ---------- node init: h, S/C tables (stride 32), AND Hs/Ht for layer 0 ----------
__global__ void __launch_bounds__(256) k_init(const float* __restrict__ bb,
      const float* __restrict__ so3, const float* __restrict__ frac,
      const float* __restrict__ W_lat, const float* __restrict__ We1){
  __shared__ float ins[8][80];
  __shared__ float hsm[8][HID];
  int base = blockIdx.x*8;
  int tid = threadIdx.x;
  for (int it = tid; it < 640; it += 256){
    int n = it/80, p = it - n*80;
    ins[n][p] = (p < BBD) ? bb[(base+n)*BBD + p] : so3[(base+n)*16 + (p-BBD)];
  }
  __syncthreads();
  int half = tid >> 7, c = tid & 127;
  float acc[4];
  #pragma unroll
  for (int n = 0; n < 4; n++){
    int node = base + half*4 + n;
    acc[n] = d_T[(node/AA)*HID + c];
  }
  #pragma unroll 4
  for (int k = 0; k < BBD; k++){
    float w = d_Wc[k*HID + c];
    #pragma unroll
    for (int n = 0; n < 4; n++) acc[n] = fmaf(ins[half*4+n][k], w, acc[n]);
  }
  #pragma unroll
  for (int k = 0; k < 16; k++){
    float w = W_lat[(HID+k)*HID + c];
    #pragma unroll
    for (int n = 0; n < 4; n++) acc[n] = fmaf(ins[half*4+n][BBD+k], w, acc[n]);
  }
  #pragma unroll
  for (int n = 0; n < 4; n++){
    d_h[(base+half*4+n)*HID + c] = acc[n];
    hsm[half*4+n][c] = acc[n];
  }
  if (tid < 240){
    int n = tid/30, k = tid - n*30;
    int dd = k/10, f = k - dd*10;
    float x = frac[(base+n)*3 + dd];
    float ang = 6.283185307179586f * (float)f * x;
    float sv, cv; sincosf(ang, &sv, &cv);
    d_S[(base+n)*32 + k] = sv;
    d_C[(base+n)*32 + k] = cv;
  }
  __syncthreads();
  // fused hsht for layer 0
  const float* W = We1 + (half*HID)*HID + c;
  float a2[8] = {0,0,0,0,0,0,0,0};
  #pragma unroll 4
  for (int k = 0; k < HID; k++){
    float w = W[k*HID];
    #pragma unroll
    for (int n = 0; n < 8; n++) a2[n] = fmaf(hsm[n][k], w, a2[n]);
  }
  float* outp = half ? d_Ht : d_Hs;
  #pragma unroll
  for (int n = 0; n < 8; n++) outp[(base+n)*HID + c] = a2[n];
}

// ---------- fused edge MLP (barrier-free, 2 blocks/graph, 512 thr, 4 islot x 4 jg) ----------
// smem float offsets
#define E_WE2 0        // 16384
#define E_WD  16384    // 7680
#define E_B2  24064    // 128
#define E_Q   24192    // 1536 [12][128]  (this block's 12 i-nodes only)
#define E_R   25728    // 3072 [24][128]
#define E_S   28800    // 768  [24][32]
#define E_C   29568    // 768
#define E_PE  30336    // 6144 [4][24][64]
#define E_G1  36480    // 12288 [4][24][128]
#define E_P   48768    // [12][4][128] = 6144
#define E_TOT 54912    // floats -> 219648 bytes

__global__ void __launch_bounds__(512,1) k_edge(const float* __restrict__ We1,
        const float* __restrict__ We2, const float* __restrict__ be2, int l){
  extern __shared__ float sm[];
  float* We2_s = sm + E_WE2;
  float* Wd_s  = sm + E_WD;
  float* b2_s  = sm + E_B2;
  float* q_s   = sm + E_Q;
  float* r_s   = sm + E_R;
  float* S_s   = sm + E_S;
  float* C_s   = sm + E_C;
  float* pe_s  = sm + E_PE;
  float* g1_s  = sm + E_G1;
  float* P_s   = sm + E_P;

  int tid = threadIdx.x;
  int g = blockIdx.x >> 1;
  int ihalf = blockIdx.x & 1;
  int nb = g*AA;

  {
    const float4* s2 = (const float4*)(We2 + l*HID*HID);
    float4* t2 = (float4*)We2_s;
    for (int it = tid; it < 4096; it += 512) t2[it] = s2[it];
    const float4* sd = (const float4*)(We1 + (l*322 + 262)*HID);
    float4* td = (float4*)Wd_s;
    for (int it = tid; it < 1920; it += 512) td[it] = sd[it];
  }
  if (tid < HID) b2_s[tid] = be2[l*HID + tid];
  // q staging: only this block's 12 i-nodes; r: all 24 j-nodes (float4)
  {
    const float4* hs4 = (const float4*)(d_Hs + (size_t)(nb + ihalf*12)*HID);
    const float4* ht4 = (const float4*)(d_Ht + (size_t)nb*HID);
    const float4* lp4 = (const float4*)(d_latc + (size_t)(l*GG + g)*HID);
    float4* q4 = (float4*)q_s;
    float4* r4 = (float4*)r_s;
    for (int it = tid; it < 12*HID/4; it += 512){
      float4 hv = hs4[it];
      float4 lv = lp4[it & 31];
      hv.x += lv.x; hv.y += lv.y; hv.z += lv.z; hv.w += lv.w;
      q4[it] = hv;
    }
    for (int it = tid; it < AA*HID/4; it += 512) r4[it] = ht4[it];
  }
  // S/C staging with float4 (stride-32 padded tables)
  {
    const float4* sS = (const float4*)(d_S + (size_t)nb*32);
    const float4* sC = (const float4*)(d_C + (size_t)nb*32);
    float4* tS = (float4*)S_s;
    float4* tC = (float4*)C_s;
    for (int it = tid; it < 192; it += 512){
      tS[it] = sS[it];
      tC[it] = sC[it];
    }
  }
  __syncthreads();

  int lane = tid & 31, warp = tid >> 5;
  int c0 = lane * 4;
  int islot = warp & 3;          // 0..3
  int jg = warp >> 2;            // 0..3 ; j set = {jg, jg+4, ..., jg+20}
  float* peW = pe_s + islot*1536;
  float* g1W = g1_s + islot*3072;

  // ---- barrier-free over all 3 ip iterations ----
  for (int ip = 0; ip < 3; ip++){
    int i0 = ihalf*12 + ip*4;
    int i = i0 + islot;
    int iloc = ip*4 + islot;     // local q index 0..11

    // warp-local pe generation (only rows this warp consumes: j in its jg set)
    if (lane < 30){
      int k = lane;
      float si = S_s[i*32+k], ci = C_s[i*32+k];
      #pragma unroll
      for (int m = 0; m < 6; m++){
        int j = jg + 4*m;
        float sj = S_s[j*32+k], cj = C_s[j*32+k];
        peW[j*64 + k]      = sj*ci - cj*si;
        peW[j*64 + 30 + k] = cj*ci + sj*si;
      }
    }
    __syncwarp();

    // phase B: g1 = silu(q_i + r_j + pe @ Wd)
    {
      float4 a[6];
      #pragma unroll
      for (int m = 0; m < 6; m++) a[m] = make_float4(0,0,0,0);
      #pragma unroll 3
      for (int k = 0; k < 60; k += 4){
        float4 p[6];
        #pragma unroll
        for (int m = 0; m < 6; m++)
          p[m] = *(const float4*)(peW + (jg + 4*m)*64 + k);
        float ps[6][4];
        #pragma unroll
        for (int m = 0; m < 6; m++){
          ps[m][0]=p[m].x; ps[m][1]=p[m].y; ps[m][2]=p[m].z; ps[m][3]=p[m].w;
        }
        #pragma unroll
        for (int kk = 0; kk < 4; kk++){
          float4 w = *(const float4*)(Wd_s + (k+kk)*HID + c0);
          #pragma unroll
          for (int m = 0; m < 6; m++) fmas(a[m], ps[m][kk], w);
        }
      }
      float4 qv = *(const float4*)(q_s + iloc*HID + c0);
      #pragma unroll
      for (int m = 0; m < 6; m++){
        int j = jg + 4*m;
        float4 rv = *(const float4*)(r_s + j*HID + c0);
        float4 x;
        x.x = silu1(qv.x + rv.x + a[m].x);
        x.y = silu1(qv.y + rv.y + a[m].y);
        x.z = silu1(qv.z + rv.z + a[m].z);
        x.w = silu1(qv.w + rv.w + a[m].w);
        *(float4*)(g1W + j*HID + c0) = x;
      }
    }
    __syncwarp();

    // phase C: per-warp partial of sum_j silu(g1 @ We2 + b2)
    {
      float4 a[6];
      #pragma unroll
      for (int m = 0; m < 6; m++) a[m] = make_float4(0,0,0,0);
      #pragma unroll 4
      for (int k = 0; k < HID; k += 4){
        float4 p[6];
        #pragma unroll
        for (int m = 0; m < 6; m++)
          p[m] = *(const float4*)(g1W + (jg + 4*m)*HID + k);
        float ps[6][4];
        #pragma unroll
        for (int m = 0; m < 6; m++){
          ps[m][0]=p[m].x; ps[m][1]=p[m].y; ps[m][2]=p[m].z; ps[m][3]=p[m].w;
        }
        #pragma unroll
        for (int kk = 0; kk < 4; kk++){
          float4 w = *(const float4*)(We2_s + (k+kk)*HID + c0);
          #pragma unroll
          for (int m = 0; m < 6; m++) fmas(a[m], ps[m][kk], w);
        }
      }
      float4 bv = *(const float4*)(b2_s + c0);
      float4 psum = make_float4(0,0,0,0);
      #pragma unroll
      for (int m = 0; m < 6; m++){
        psum.x += silu1(a[m].x + bv.x);
        psum.y += silu1(a[m].y + bv.y);
        psum.z += silu1(a[m].z + bv.z);
        psum.w += silu1(a[m].w + bv.w);
      }
      // private slot: [node-in-block = ip*4+islot][jg][c]
      *(float4*)(P_s + iloc*512 + jg*128 + c0) = psum;
    }
  }
  __syncthreads();

  // ---- final reduction: 12 nodes x 128 cols, 4 jg-partials each (float4) ----
  {
    float4* agg4 = (float4*)(d_agg + (size_t)(nb + ihalf*12)*HID);
    for (int it = tid; it < 12*HID/4; it += 512){
      int n = it >> 5, cq = it & 31;               // cq = c/4
      const float4* pp = (const float4*)(P_s + n*512) + cq;
      float4 s0 = pp[0], s1 = pp[32], s2 = pp[64], s3 = pp[96];
      float4 o;
      o.x = (s0.x + s1.x + s2.x + s3.x) * (1.0f/24.0f);
      o.y = (s0.y + s1.y + s2.y + s3.y) * (1.0f/24.0f);
      o.z = (s0.z + s1.z + s2.z + s3.z) * (1.0f/24.0f);
      o.w = (s0.w + s1.w + s2.w + s3.w) * (1.0f/24.0f);
      agg4[it] = o;
    }
  }
}

// ---------- node MLP + fused hsht for layer l+1 ----------
__global__ void __launch_bounds__(256) k_node(const float* __restrict__ Wn1,
      const float* __restrict__ bn1, const float* __restrict__ Wn2,
      const float* __restrict__ bn2, const float* __restrict__ We1, int l){
  __shared__ float nin[8][256];
  __shared__ float t1s[8][HID];
  int base = blockIdx.x*8;
  int tid = threadIdx.x;
  for (int it = tid; it < 8*256; it += 256){
    int n = it >> 8, k = it & 255;
    nin[n][k] = (k < HID) ? d_h[(base+n)*HID + k] : d_agg[(base+n)*HID + (k-HID)];
  }
  __syncthreads();
  int half = tid >> 7, c = tid & 127;
  float acc[4];
  float b1 = bn1[l*HID + c];
  #pragma unroll
  for (int n = 0; n < 4; n++) acc[n] = b1;
  const float* W1 = Wn1 + (l*256)*HID + c;
  #pragma unroll 4
  for (int k = 0; k < 256; k++){
    float w = W1[k*HID];
    #pragma unroll
    for (int n = 0; n < 4; n++) acc[n] = fmaf(nin[half*4+n][k], w, acc[n]);
  }
  #pragma unroll
  for (int n = 0; n < 4; n++) t1s[half*4+n][c] = silu1(acc[n]);
  __syncthreads();
  float b2 = bn2[l*HID + c];
  #pragma unroll
  for (int n = 0; n < 4; n++) acc[n] = b2;
  const float* W2 = Wn2 + (l*HID)*HID + c;
  #pragma unroll 4
  for (int k = 0; k < HID; k++){
    float w = W2[k*HID];
    #pragma unroll
    for (int n = 0; n < 4; n++) acc[n] = fmaf(t1s[half*4+n][k], w, acc[n]);
  }
  #pragma unroll
  for (int n = 0; n < 4; n++){
    int node = base + half*4 + n;
    float hn = nin[half*4+n][c] + silu1(acc[n]);
    d_h[node*HID + c] = hn;
    nin[half*4+n][HID + c] = hn;       // stash for fused hsht
  }
  if (l < NL-1){
    __syncthreads();
    const float* W = We1 + ((l+1)*322 + half*HID)*HID + c;
    float a2[8] = {0,0,0,0,0,0,0,0};
    #pragma unroll 4
    for (int k = 0; k < HID; k++){
      float w = W[k*HID];
      #pragma unroll
      for (int n = 0; n < 8; n++) a2[n] = fmaf(nin[n][HID + k], w, a2[n]);
    }
    float* outp = half ? d_Ht : d_Hs;
    #pragma unroll
    for (int n = 0; n < 8; n++) outp[(base+n)*HID + c] = a2[n];
  }
}

// ---------- outputs: lattice (G*6), coord (N*3), so3 (N*4) ----------
__global__ void __launch_bounds__(128) k_out(const float* __restrict__ frac,
      const float* __restrict__ W_coord, const float* __restrict__ W_lattice,
      const float* __restrict__ W_so3, float* __restrict__ out){
  __shared__ float hsm[AA*129];
  __shared__ float gf[HID];
  int g = blockIdx.x, nb = g*AA;
  int tid = threadIdx.x;
  for (int it = tid; it < AA*HID; it += 128){
    int n = it >> 7, k = it & 127;
    hsm[n*129 + k] = d_h[(nb+n)*HID + k];
  }
  __syncthreads();
  {
    float s = 0.f;
    #pragma unroll
    for (int n = 0; n < AA; n++) s += hsm[n*129 + tid];
    gf[tid] = s * (1.0f/24.0f);
  }
  __syncthreads();
  if (tid < 6){
    float s = 0.f;
    #pragma unroll 8
    for (int k = 0; k < HID; k++) s = fmaf(gf[k], W_lattice[k*6 + tid], s);
    out[g*6 + tid] = s;
  }
  if (tid < AA){
    int n = tid;
    const float* hr = hsm + n*129;
    #pragma unroll
    for (int o = 0; o < 3; o++){
      float s = 0.f;
      #pragma unroll 8
      for (int k = 0; k < HID; k++) s = fmaf(hr[k], W_coord[k*3 + o], s);
      float v = s + frac[(nb+n)*3 + o];
      out[GG*6 + (nb+n)*3 + o] = v - floorf(v);
    }
    float so[4];
    #pragma unroll
    for (int o = 0; o < 4; o++){
      float s = 0.f;
      #pragma unroll 8
      for (int k = 0; k < HID; k++) s = fmaf(hr[k], W_so3[k*4 + o], s);
      so[o] = s;
    }
    float nrm = sqrtf(so[0]*so[0] + so[1]*so[1] + so[2]*so[2] + so[3]*so[3]);
    float inv = 1.0f / nrm;
    #pragma unroll
    for (int o = 0; o < 4; o++)
      out[GG*6 + NN*3 + (nb+n)*4 + o] = so[o] * inv;
  }
}

extern "C" void kernel_launch(void* const* d_in, const int* in_sizes, int n_in,
                              void* d_out, int out_size){
  const float* t      = (const float*)d_in[0];
  const float* bb     = (const float*)d_in[1];
  const float* frac   = (const float*)d_in[2];
  const float* so3    = (const float*)d_in[3];
  const float* latt   = (const float*)d_in[4];
  const float* W_emb  = (const float*)d_in[8];
  const float* b_emb  = (const float*)d_in[9];
  const float* W_lat  = (const float*)d_in[10];
  const float* b_lat  = (const float*)d_in[11];
  const float* We1    = (const float*)d_in[12];
  const float* be1    = (const float*)d_in[13];
  const float* We2    = (const float*)d_in[14];
  const float* be2    = (const float*)d_in[15];
  const float* Wn1    = (const float*)d_in[16];
  const float* bn1    = (const float*)d_in[17];
  const float* Wn2    = (const float*)d_in[18];
  const float* bn2    = (const float*)d_in[19];
  const float* W_coord   = (const float*)d_in[20];
  const float* W_lattice = (const float*)d_in[21];
  const float* W_so3     = (const float*)d_in[22];
  float* out = (float*)d_out;

  cudaFuncSetAttribute(k_edge, cudaFuncAttributeMaxDynamicSharedMemorySize,
                       E_TOT * (int)sizeof(float));

  k_wce <<<BBD+1, 128>>>(W_emb, b_emb, W_lat, b_lat);
  k_T   <<<GG, 128>>>(t, W_lat);
  k_latc<<<(NL*GG*HID)/256, 256>>>(latt, We1, be1);
  k_init<<<NN/8, 256>>>(bb, so3, frac, W_lat, We1);
  for (int l = 0; l < NL; l++){
    k_edge<<<GG*2, 512, E_TOT*(int)sizeof(float)>>>(We1, We2, be2, l);
    k_node<<<NN/8, 256>>>(Wn1, bn1, Wn2, bn2, We1, l);
  }
  k_out<<<GG, 128>>>(frac, W_coord, W_lattice, W_so3, out);
}